// round 7
// baseline (speedup 1.0000x reference)
#include <cuda_runtime.h>
#include <math.h>
#include <stdint.h>

#define Bn   128
#define Tn   200
#define Vn   50257
#define Hn   256
#define En   128
#define OOV  50
#define H2   512
#define XD   640
#define PV   (Vn + OOV)
#define NTILES 393          // ceil(Vn/128)
#define CTILES 400          // 25600/64

__device__ float g_score[(size_t)Bn * Vn];   // holds exp(score - tile_max)
__device__ float g_scorec[Bn * Tn];
__device__ float g_pm[Bn * NTILES];          // tile max
__device__ float g_ps[Bn * NTILES];          // tile sumexp -> then scale
__device__ float g_max[Bn];
__device__ float g_invsum[Bn];

// ============================ helpers =======================================
__device__ __forceinline__ uint32_t tf32_rna(float x) {
    uint32_t r;
    asm("cvt.rna.tf32.f32 %0, %1;" : "=r"(r) : "f"(x));
    return r;
}
// FMA-only exp: ~1e-7 rel err, no MUFU. Valid output 0 for x <= -87.
__device__ __forceinline__ float fexp(float x) {
    x = fminf(fmaxf(x, -87.0f), 87.0f);
    float y = x * 1.4426950408889634f;              // log2(e)
    float z = y + 12582912.f;                       // round-to-nearest magic
    int   i = __float_as_int(z) - 0x4B400000;
    float f = y - (z - 12582912.f);                 // f in [-0.5, 0.5]
    float p = 1.3386276e-3f;
    p = fmaf(p, f, 9.6183633e-3f);
    p = fmaf(p, f, 5.5502813e-2f);
    p = fmaf(p, f, 2.4022652e-1f);
    p = fmaf(p, f, 6.9314720e-1f);
    p = fmaf(p, f, 1.0f);
    return __int_as_float(__float_as_int(p) + (i << 23));
}
// FMA-only tanh: fexp + bit-trick reciprocal (3 Newton steps), no MUFU.
__device__ __forceinline__ float ftanh(float x) {
    float ax = fminf(fabsf(x), 15.f);
    float t  = fexp(2.f * ax);                      // e^{2|x|} in [1, 1.07e13]
    float d  = t + 1.f;
    float r  = __int_as_float(0x7EF311C3u - __float_as_int(d));
    r = r * fmaf(-d, r, 2.f);
    r = r * fmaf(-d, r, 2.f);
    r = r * fmaf(-d, r, 2.f);
    float th = (t - 1.f) * r;
    return copysignf(th, x);
}
// m16n8k8 tf32 MMA (sm_80+ baseline; assembles for plain sm_103)
__device__ __forceinline__ void mma_tf32(float c[4], const uint32_t a[4],
                                         const uint32_t b[2]) {
    asm volatile(
        "mma.sync.aligned.m16n8k8.row.col.f32.tf32.tf32.f32 "
        "{%0,%1,%2,%3}, {%4,%5,%6,%7}, {%8,%9}, {%0,%1,%2,%3};"
        : "+f"(c[0]), "+f"(c[1]), "+f"(c[2]), "+f"(c[3])
        : "r"(a[0]), "r"(a[1]), "r"(a[2]), "r"(a[3]), "r"(b[0]), "r"(b[1]));
}

// ---------------------------------------------------------------------------
// Kernel A: GRU cell. 4 batches per block (grid 32), 256 threads.
// ---------------------------------------------------------------------------
__global__ __launch_bounds__(256) void gru_kernel(
    const int* __restrict__ dec_in, const float* __restrict__ enc,
    const int* __restrict__ step,
    const float* __restrict__ prev_state, const float* __restrict__ sel,
    const float* __restrict__ emb,
    const float* __restrict__ W_ih, const float* __restrict__ W_hh,
    const float* __restrict__ b_ih, const float* __restrict__ b_hh,
    const float* __restrict__ Wi_w, const float* __restrict__ Wi_b,
    float* __restrict__ dh_out)
{
    __shared__ __align__(16) float xs[4][XD];
    __shared__ __align__(16) float hs[4][Hn];
    __shared__ __align__(16) float es[4][H2];

    const int b0  = blockIdx.x * 4;
    const int tid = threadIdx.x;
    const int stepv = step ? step[0] : 1;

    for (int i = tid; i < 4 * H2; i += 256) {
        int bb = i >> 9, v = i & 511;
        xs[bb][v] = stepv ? sel[(b0 + bb) * H2 + v] : 0.f;
    }
    for (int i = tid; i < 4 * En; i += 256) {
        int bb = i >> 7, v = i & 127;
        xs[bb][H2 + v] = emb[(size_t)dec_in[b0 + bb] * En + v];
    }
    if (stepv) {
        for (int i = tid; i < 4 * Hn; i += 256) {
            int bb = i >> 8, v = i & 255;
            hs[bb][v] = prev_state[(b0 + bb) * Hn + v];
        }
        __syncthreads();
    } else {
        for (int i = tid; i < 4 * H2; i += 256) {
            int bb = i >> 9, v = i & 511;
            es[bb][v] = enc[((size_t)(b0 + bb) * Tn + (Tn - 1)) * H2 + v];
        }
        __syncthreads();
        const int j = tid;
        const float4* wr = (const float4*)(Wi_w + (size_t)j * H2);
        float bj = Wi_b[j];
        float acc[4] = {bj, bj, bj, bj};
        for (int k = 0; k < H2 / 4; k++) {
            float4 w = wr[k];
            #pragma unroll
            for (int bb = 0; bb < 4; bb++) {
                float4 e = ((const float4*)es[bb])[k];
                acc[bb] += w.x * e.x + w.y * e.y + w.z * e.z + w.w * e.w;
            }
        }
        #pragma unroll
        for (int bb = 0; bb < 4; bb++) hs[bb][j] = acc[bb];
        __syncthreads();
    }

    const int j = tid;
    float gir[4], giz[4], gin[4], ghr[4], ghz[4], ghn[4];
    {
        float v0 = b_ih[j], v1 = b_ih[Hn + j], v2 = b_ih[2 * Hn + j];
        #pragma unroll
        for (int bb = 0; bb < 4; bb++) { gir[bb] = v0; giz[bb] = v1; gin[bb] = v2; }
        const float4* r0 = (const float4*)(W_ih + (size_t)j * XD);
        const float4* r1 = (const float4*)(W_ih + (size_t)(Hn + j) * XD);
        const float4* r2 = (const float4*)(W_ih + (size_t)(2 * Hn + j) * XD);
        for (int k = 0; k < XD / 4; k++) {
            float4 w0 = r0[k], w1 = r1[k], w2 = r2[k];
            #pragma unroll
            for (int bb = 0; bb < 4; bb++) {
                float4 x = ((const float4*)xs[bb])[k];
                gir[bb] += w0.x * x.x + w0.y * x.y + w0.z * x.z + w0.w * x.w;
                giz[bb] += w1.x * x.x + w1.y * x.y + w1.z * x.z + w1.w * x.w;
                gin[bb] += w2.x * x.x + w2.y * x.y + w2.z * x.z + w2.w * x.w;
            }
        }
    }
    {
        float v0 = b_hh[j], v1 = b_hh[Hn + j], v2 = b_hh[2 * Hn + j];
        #pragma unroll
        for (int bb = 0; bb < 4; bb++) { ghr[bb] = v0; ghz[bb] = v1; ghn[bb] = v2; }
        const float4* r0 = (const float4*)(W_hh + (size_t)j * Hn);
        const float4* r1 = (const float4*)(W_hh + (size_t)(Hn + j) * Hn);
        const float4* r2 = (const float4*)(W_hh + (size_t)(2 * Hn + j) * Hn);
        for (int k = 0; k < Hn / 4; k++) {
            float4 w0 = r0[k], w1 = r1[k], w2 = r2[k];
            #pragma unroll
            for (int bb = 0; bb < 4; bb++) {
                float4 x = ((const float4*)hs[bb])[k];
                ghr[bb] += w0.x * x.x + w0.y * x.y + w0.z * x.z + w0.w * x.w;
                ghz[bb] += w1.x * x.x + w1.y * x.y + w1.z * x.z + w1.w * x.w;
                ghn[bb] += w2.x * x.x + w2.y * x.y + w2.z * x.z + w2.w * x.w;
            }
        }
    }
    #pragma unroll
    for (int bb = 0; bb < 4; bb++) {
        float r = 1.f / (1.f + fexp(-(gir[bb] + ghr[bb])));
        float z = 1.f / (1.f + fexp(-(giz[bb] + ghz[bb])));
        float n = ftanh(gin[bb] + r * ghn[bb]);
        dh_out[(b0 + bb) * Hn + j] = (1.f - z) * n + z * hs[bb][j];
    }
}

// ---------------------------------------------------------------------------
// Kernel B: score_g via mma.sync tf32. Block 128x128xK256, warp 64x32.
// Epilogue: bias + exp(val - tile_max) stored to g_score + partial max/sum.
// ---------------------------------------------------------------------------
__global__ __launch_bounds__(256) void scoreg_mma(
    const float* __restrict__ dh, const float* __restrict__ Wg,
    const float* __restrict__ Wgb)
{
    extern __shared__ __align__(16) float dyn[];
    float* As = dyn;                 // [128][68]
    float* Bs = dyn + 128 * 68;      // [128][68]
    __shared__ float biasS[128];

    const int tid  = threadIdx.x;
    const int wid  = tid >> 5, lane = tid & 31;
    const int warpM = wid >> 2, warpN = wid & 3;
    const int lr = lane >> 2, lc = lane & 3;
    const int v0 = blockIdx.x * 128;
    const int nvalid = (Vn - v0 < 128) ? (Vn - v0) : 128;

    if (tid < 128) {
        int vg = v0 + tid;
        biasS[tid] = (vg < Vn) ? Wgb[vg] : 0.f;
    }

    float acc[4][4][4];
    #pragma unroll
    for (int mi = 0; mi < 4; mi++)
        #pragma unroll
        for (int ni = 0; ni < 4; ni++)
            #pragma unroll
            for (int q = 0; q < 4; q++) acc[mi][ni][q] = 0.f;

    for (int kc = 0; kc < 4; kc++) {
        #pragma unroll
        for (int p = 0; p < 8; p++) {            // A = dh (128 x 64)
            int idx = tid + p * 256;
            int m = idx >> 4, c4 = (idx & 15) * 4;
            float4 v = *(const float4*)(dh + m * 256 + kc * 64 + c4);
            float* d = &As[m * 68 + c4];
            d[0] = __uint_as_float(tf32_rna(v.x));
            d[1] = __uint_as_float(tf32_rna(v.y));
            d[2] = __uint_as_float(tf32_rna(v.z));
            d[3] = __uint_as_float(tf32_rna(v.w));
        }
        #pragma unroll
        for (int p = 0; p < 8; p++) {            // B = Wg (128 x 64)
            int idx = tid + p * 256;
            int n = idx >> 4, c4 = (idx & 15) * 4;
            int vg = v0 + n;
            float4 v = (vg < Vn) ? *(const float4*)(Wg + (size_t)vg * 256 + kc * 64 + c4)
                                 : make_float4(0.f, 0.f, 0.f, 0.f);
            float* d = &Bs[n * 68 + c4];
            d[0] = __uint_as_float(tf32_rna(v.x));
            d[1] = __uint_as_float(tf32_rna(v.y));
            d[2] = __uint_as_float(tf32_rna(v.z));
            d[3] = __uint_as_float(tf32_rna(v.w));
        }
        __syncthreads();
        #pragma unroll
        for (int k0 = 0; k0 < 64; k0 += 8) {
            uint32_t af[4][4], bf[4][2];
            #pragma unroll
            for (int mi = 0; mi < 4; mi++) {
                int row = warpM * 64 + mi * 16 + lr;
                af[mi][0] = __float_as_uint(As[row * 68 + k0 + lc]);
                af[mi][1] = __float_as_uint(As[(row + 8) * 68 + k0 + lc]);
                af[mi][2] = __float_as_uint(As[row * 68 + k0 + 4 + lc]);
                af[mi][3] = __float_as_uint(As[(row + 8) * 68 + k0 + 4 + lc]);
            }
            #pragma unroll
            for (int ni = 0; ni < 4; ni++) {
                int n = warpN * 32 + ni * 8 + lr;
                bf[ni][0] = __float_as_uint(Bs[n * 68 + k0 + lc]);
                bf[ni][1] = __float_as_uint(Bs[n * 68 + k0 + 4 + lc]);
            }
            #pragma unroll
            for (int mi = 0; mi < 4; mi++)
                #pragma unroll
                for (int ni = 0; ni < 4; ni++)
                    mma_tf32(acc[mi][ni], af[mi], bf[ni]);
        }
        __syncthreads();
    }

    // stage val+bias into smem [128][132]
    float* stg = dyn;
    #pragma unroll
    for (int mi = 0; mi < 4; mi++) {
        int row = warpM * 64 + mi * 16 + lr;
        #pragma unroll
        for (int ni = 0; ni < 4; ni++) {
            int col = warpN * 32 + ni * 8 + 2 * lc;
            stg[row * 132 + col]           = acc[mi][ni][0] + biasS[col];
            stg[row * 132 + col + 1]       = acc[mi][ni][1] + biasS[col + 1];
            stg[(row + 8) * 132 + col]     = acc[mi][ni][2] + biasS[col];
            stg[(row + 8) * 132 + col + 1] = acc[mi][ni][3] + biasS[col + 1];
        }
    }
    __syncthreads();

    // warp-per-row epilogue: row max, e=exp(v-max), sum, store e
    for (int rb = 0; rb < 16; rb++) {
        int r = wid * 16 + rb;
        float v[4];
        #pragma unroll
        for (int q = 0; q < 4; q++) {
            int c = lane * 4 + q;
            v[q] = (c < nvalid) ? stg[r * 132 + c] : -INFINITY;
        }
        float m = fmaxf(fmaxf(v[0], v[1]), fmaxf(v[2], v[3]));
        #pragma unroll
        for (int off = 16; off > 0; off >>= 1)
            m = fmaxf(m, __shfl_xor_sync(0xffffffffu, m, off));
        float e[4], s = 0.f;
        #pragma unroll
        for (int q = 0; q < 4; q++) { e[q] = fexp(v[q] - m); s += e[q]; }
        #pragma unroll
        for (int off = 16; off > 0; off >>= 1)
            s += __shfl_xor_sync(0xffffffffu, s, off);
        #pragma unroll
        for (int q = 0; q < 4; q++) {
            int c = lane * 4 + q;
            if (c < nvalid) g_score[(size_t)r * Vn + v0 + c] = e[q];
        }
        if (lane == 0) {
            g_pm[r * NTILES + blockIdx.x] = m;
            g_ps[r * NTILES + blockIdx.x] = s;
        }
    }
}

// ---------------------------------------------------------------------------
// Kernel C: score_c via mma.sync tf32 over flattened enc (25600 x 512).
// Block 64x256xK512, warp 32x64. Epilogue: tanh(P+b).dh -> tanh -> mask.
// ---------------------------------------------------------------------------
__global__ __launch_bounds__(256) void scorec_mma(
    const float* __restrict__ enc, const int* __restrict__ encIdx,
    const float* __restrict__ Wc, const float* __restrict__ Wcb,
    const float* __restrict__ dh)
{
    extern __shared__ __align__(16) float dyn[];
    float* As = dyn;                 // [64][68]
    float* Bs = dyn + 64 * 68;       // [256][68]
    __shared__ float biasS[256];
    __shared__ float dh2[2][256];
    __shared__ float red[64][4];

    const int tid  = threadIdx.x;
    const int wid  = tid >> 5, lane = tid & 31;
    const int warpM = wid >> 2, warpN = wid & 3;
    const int lr = lane >> 2, lc = lane & 3;
    const int r0 = blockIdx.x * 64;
    const int b0 = r0 / Tn;
    const int b1 = (b0 + 1 < Bn) ? b0 + 1 : Bn - 1;

    biasS[tid] = Wcb[tid];
    for (int i = tid; i < 512; i += 256) {
        int w = i >> 8;
        dh2[w][i & 255] = dh[(w ? b1 : b0) * 256 + (i & 255)];
    }

    float acc[2][8][4];
    #pragma unroll
    for (int mi = 0; mi < 2; mi++)
        #pragma unroll
        for (int ni = 0; ni < 8; ni++)
            #pragma unroll
            for (int q = 0; q < 4; q++) acc[mi][ni][q] = 0.f;

    for (int kc = 0; kc < 8; kc++) {
        #pragma unroll
        for (int p = 0; p < 4; p++) {            // A = enc (64 x 64)
            int idx = tid + p * 256;
            int m = idx >> 4, c4 = (idx & 15) * 4;
            float4 v = *(const float4*)(enc + (size_t)(r0 + m) * 512 + kc * 64 + c4);
            float* d = &As[m * 68 + c4];
            d[0] = __uint_as_float(tf32_rna(v.x));
            d[1] = __uint_as_float(tf32_rna(v.y));
            d[2] = __uint_as_float(tf32_rna(v.z));
            d[3] = __uint_as_float(tf32_rna(v.w));
        }
        #pragma unroll
        for (int p = 0; p < 16; p++) {           // B = Wc (256 x 64)
            int idx = tid + p * 256;
            int n = idx >> 4, c4 = (idx & 15) * 4;
            float4 v = *(const float4*)(Wc + (size_t)n * 512 + kc * 64 + c4);
            float* d = &Bs[n * 68 + c4];
            d[0] = __uint_as_float(tf32_rna(v.x));
            d[1] = __uint_as_float(tf32_rna(v.y));
            d[2] = __uint_as_float(tf32_rna(v.z));
            d[3] = __uint_as_float(tf32_rna(v.w));
        }
        __syncthreads();
        #pragma unroll
        for (int k0 = 0; k0 < 64; k0 += 8) {
            uint32_t af[2][4], bf[8][2];
            #pragma unroll
            for (int mi = 0; mi < 2; mi++) {
                int row = warpM * 32 + mi * 16 + lr;
                af[mi][0] = __float_as_uint(As[row * 68 + k0 + lc]);
                af[mi][1] = __float_as_uint(As[(row + 8) * 68 + k0 + lc]);
                af[mi][2] = __float_as_uint(As[row * 68 + k0 + 4 + lc]);
                af[mi][3] = __float_as_uint(As[(row + 8) * 68 + k0 + 4 + lc]);
            }
            #pragma unroll
            for (int ni = 0; ni < 8; ni++) {
                int n = warpN * 64 + ni * 8 + lr;
                bf[ni][0] = __float_as_uint(Bs[n * 68 + k0 + lc]);
                bf[ni][1] = __float_as_uint(Bs[n * 68 + k0 + 4 + lc]);
            }
            #pragma unroll
            for (int mi = 0; mi < 2; mi++)
                #pragma unroll
                for (int ni = 0; ni < 8; ni++)
                    mma_tf32(acc[mi][ni], af[mi], bf[ni]);
        }
        __syncthreads();
    }

    // epilogue: per-row sum over this warp's 64 h-columns of tanh(v+b)*dh
    #pragma unroll
    for (int mi = 0; mi < 2; mi++) {
        int rowa = warpM * 32 + mi * 16 + lr;
        int rowb = rowa + 8;
        int ba = (r0 + rowa) / Tn - b0;
        int bb = (r0 + rowb) / Tn - b0;
        float pa = 0.f, pb = 0.f;
        #pragma unroll
        for (int ni = 0; ni < 8; ni++) {
            int col = warpN * 64 + ni * 8 + 2 * lc;
            float t0 = ftanh(acc[mi][ni][0] + biasS[col]);
            float t1 = ftanh(acc[mi][ni][1] + biasS[col + 1]);
            float t2 = ftanh(acc[mi][ni][2] + biasS[col]);
            float t3 = ftanh(acc[mi][ni][3] + biasS[col + 1]);
            pa += t0 * dh2[ba][col] + t1 * dh2[ba][col + 1];
            pb += t2 * dh2[bb][col] + t3 * dh2[bb][col + 1];
        }
        pa += __shfl_xor_sync(0xffffffffu, pa, 1);
        pa += __shfl_xor_sync(0xffffffffu, pa, 2);
        pb += __shfl_xor_sync(0xffffffffu, pb, 1);
        pb += __shfl_xor_sync(0xffffffffu, pb, 2);
        if (lc == 0) {
            red[rowa][warpN] = pa;
            red[rowb][warpN] = pb;
        }
    }
    __syncthreads();
    if (tid < 64) {
        float s = red[tid][0] + red[tid][1] + red[tid][2] + red[tid][3];
        float sc = ftanh(s);
        int gr = r0 + tid;
        if (encIdx[gr] == 0) sc -= 10000.f;
        g_scorec[gr] = sc;
    }
}

// ---------------------------------------------------------------------------
// Kernel D: combine partials; rewrite g_ps as per-tile probability scale.
// ---------------------------------------------------------------------------
__global__ __launch_bounds__(256) void combine_kernel()
{
    __shared__ float red[256];
    const int b = blockIdx.x, tid = threadIdx.x;

    float m = -INFINITY;
    for (int i = tid; i < NTILES; i += 256) m = fmaxf(m, g_pm[b * NTILES + i]);
    for (int i = tid; i < Tn; i += 256)     m = fmaxf(m, g_scorec[b * Tn + i]);
    red[tid] = m; __syncthreads();
    for (int s = 128; s > 0; s >>= 1) {
        if (tid < s) red[tid] = fmaxf(red[tid], red[tid + s]);
        __syncthreads();
    }
    float mx = red[0];
    __syncthreads();

    float s = 0.f;
    for (int i = tid; i < NTILES; i += 256)
        s += g_ps[b * NTILES + i] * fexp(g_pm[b * NTILES + i] - mx);
    for (int i = tid; i < Tn; i += 256)
        s += fexp(g_scorec[b * Tn + i] - mx);
    red[tid] = s; __syncthreads();
    for (int k = 128; k > 0; k >>= 1) {
        if (tid < k) red[tid] += red[tid + k];
        __syncthreads();
    }
    float inv = 1.f / red[0];
    if (tid == 0) { g_max[b] = mx; g_invsum[b] = inv; }
    __syncthreads();
    // overwrite g_ps with the per-tile scale used by probg
    for (int i = tid; i < NTILES; i += 256)
        g_ps[b * NTILES + i] = fexp(g_pm[b * NTILES + i] - mx) * inv;
}

// ---------------------------------------------------------------------------
// Kernel E: prob_out base = [ e * tile_scale (V) | 1e-4 (OOV) ]. No exp.
// ---------------------------------------------------------------------------
__global__ __launch_bounds__(256) void probg_kernel(float* __restrict__ out)
{
    int idx = blockIdx.x * 256 + threadIdx.x;
    if (idx >= Bn * PV) return;
    int b = idx / PV, v = idx - b * PV;
    out[idx] = (v < Vn)
        ? g_score[(size_t)b * Vn + v] * g_ps[b * NTILES + (v >> 7)]
        : 1e-4f;
}

// ---------------------------------------------------------------------------
// Kernel F: prob_c, scatter-add into prob_out, selective_read_new.
// ---------------------------------------------------------------------------
__global__ __launch_bounds__(256) void final_kernel(
    const int* __restrict__ dec_in, const int* __restrict__ encIdx,
    const float* __restrict__ enc,
    float* __restrict__ prob_out, float* __restrict__ sel_out)
{
    __shared__ float pc[Tn];
    __shared__ float wt[Tn];
    __shared__ float norm;

    const int b = blockIdx.x, tid = threadIdx.x;
    const float mx = g_max[b], inv = g_invsum[b];
    const int dec = dec_in[b];

    if (tid < Tn) {
        float p = fexp(g_scorec[b * Tn + tid] - mx) * inv;
        pc[tid] = p;
        wt[tid] = (encIdx[b * Tn + tid] == dec) ? 1.f : 0.f;
    }
    __syncthreads();
    if (tid == 0) {
        float t = 0.f;
        for (int i = 0; i < Tn; i++) t += wt[i];
        norm = (t > 1.f) ? 1.f / t : 1.f;
    }
    __syncthreads();
    float nf = norm;
    if (tid < Tn) {
        wt[tid] = wt[tid] * pc[tid] * nf;
        atomicAdd(&prob_out[(size_t)b * PV + encIdx[b * Tn + tid]], pc[tid]);
    }
    __syncthreads();

    const float* encb = enc + (size_t)b * Tn * H2;
    for (int e = tid; e < H2; e += 256) {
        float s = 0.f;
        #pragma unroll 4
        for (int t = 0; t < Tn; t++) s += wt[t] * encb[(size_t)t * H2 + e];
        sel_out[b * H2 + e] = s;
    }
}

// ---------------------------------------------------------------------------
extern "C" void kernel_launch(void* const* d_in, const int* in_sizes, int n_in,
                              void* d_out, int out_size)
{
    const int*   dec  = (const int*)d_in[0];
    const float* enc  = (const float*)d_in[1];
    const int*   eidx = (const int*)d_in[2];
    const float* prev = (const float*)d_in[3];
    const float* sel  = (const float*)d_in[4];
    const int si = (n_in >= 17) ? 1 : 0;
    const int* step = si ? (const int*)d_in[5] : nullptr;
    const float* emb = (const float*)d_in[5 + si];
    const float* Wih = (const float*)d_in[6 + si];
    const float* Whh = (const float*)d_in[7 + si];
    const float* bih = (const float*)d_in[8 + si];
    const float* bhh = (const float*)d_in[9 + si];
    const float* Wiw = (const float*)d_in[10 + si];
    const float* Wib = (const float*)d_in[11 + si];
    const float* Wgw = (const float*)d_in[12 + si];
    const float* Wgb = (const float*)d_in[13 + si];
    const float* Wcw = (const float*)d_in[14 + si];
    const float* Wcb = (const float*)d_in[15 + si];

    float* out    = (float*)d_out;
    float* prob   = out;                       // (B, 1, V+OOV)
    float* dh     = out + (size_t)Bn * PV;     // (B, H)
    float* selnew = dh + Bn * Hn;              // (B, 1, 2H)

    const int SMEM_G = 2 * 128 * 68 * 4;                 // 69632 B
    const int SMEM_C = (64 * 68 + 256 * 68) * 4;         // 87040 B
    cudaFuncSetAttribute(scoreg_mma, cudaFuncAttributeMaxDynamicSharedMemorySize, SMEM_G);
    cudaFuncSetAttribute(scorec_mma, cudaFuncAttributeMaxDynamicSharedMemorySize, SMEM_C);

    gru_kernel<<<Bn / 4, 256>>>(dec, enc, step, prev, sel, emb, Wih, Whh,
                                bih, bhh, Wiw, Wib, dh);
    scoreg_mma<<<NTILES, 256, SMEM_G>>>(dh, Wgw, Wgb);
    scorec_mma<<<CTILES, 256, SMEM_C>>>(enc, eidx, Wcw, Wcb, dh);
    combine_kernel<<<Bn, 256>>>();
    probg_kernel<<<(Bn * PV + 255) / 256, 256>>>(prob);
    final_kernel<<<Bn, 256>>>(dec, eidx, enc, prob, selnew);
}

// round 10
// speedup vs baseline: 1.1124x; 1.1124x over previous
#include <cuda_runtime.h>
#include <cuda_fp16.h>
#include <math.h>
#include <stdint.h>

#define Bn   128
#define Tn   200
#define Vn   50257
#define Hn   256
#define En   128
#define OOV  50
#define H2   512
#define XD   640
#define PV   (Vn + OOV)
#define NTILES 393          // ceil(Vn/128)
#define VPAD  (NTILES * 128)
#define CTILES 400          // 25600/64

__device__ float g_score[(size_t)Bn * Vn];   // exp(score - tile_max)
__device__ float g_scorec[Bn * Tn];
__device__ float g_pm[Bn * NTILES];
__device__ float g_ps[Bn * NTILES];
__device__ float g_max[Bn];
__device__ float g_invsum[Bn];
__device__ __half g_WgH[(size_t)VPAD * Hn];          // fp16 Wg (padded rows zero)
__device__ __half g_encH[(size_t)Bn * Tn * H2];      // fp16 enc
__device__ __half g_WcH[Hn * H2];                    // fp16 Wc

// ============================ helpers =======================================
__device__ __forceinline__ uint32_t smem_u32(const void* p) {
    uint32_t a;
    asm("{ .reg .u64 t; cvta.to.shared.u64 t, %1; cvt.u32.u64 %0, t; }"
        : "=r"(a) : "l"(p));
    return a;
}
__device__ __forceinline__ float fexp(float x) {
    x = fminf(fmaxf(x, -87.0f), 87.0f);
    float y = x * 1.4426950408889634f;
    float z = y + 12582912.f;
    int   i = __float_as_int(z) - 0x4B400000;
    float f = y - (z - 12582912.f);
    float p = 1.3386276e-3f;
    p = fmaf(p, f, 9.6183633e-3f);
    p = fmaf(p, f, 5.5502813e-2f);
    p = fmaf(p, f, 2.4022652e-1f);
    p = fmaf(p, f, 6.9314720e-1f);
    p = fmaf(p, f, 1.0f);
    return __int_as_float(__float_as_int(p) + (i << 23));
}
__device__ __forceinline__ float ftanh(float x) {
    float ax = fminf(fabsf(x), 15.f);
    float t  = fexp(2.f * ax);
    float d  = t + 1.f;
    float r  = __int_as_float(0x7EF311C3u - __float_as_int(d));
    r = r * fmaf(-d, r, 2.f);
    r = r * fmaf(-d, r, 2.f);
    r = r * fmaf(-d, r, 2.f);
    return copysignf((t - 1.f) * r, x);
}
__device__ __forceinline__ void mma_f16(float c[4], const uint32_t a[4],
                                        const uint32_t b[2]) {
    asm volatile(
        "mma.sync.aligned.m16n8k16.row.col.f32.f16.f16.f32 "
        "{%0,%1,%2,%3}, {%4,%5,%6,%7}, {%8,%9}, {%0,%1,%2,%3};"
        : "+f"(c[0]), "+f"(c[1]), "+f"(c[2]), "+f"(c[3])
        : "r"(a[0]), "r"(a[1]), "r"(a[2]), "r"(a[3]), "r"(b[0]), "r"(b[1]));
}
__device__ __forceinline__ void cpa16(uint32_t d, const void* s) {
    asm volatile("cp.async.cg.shared.global [%0], [%1], 16;" :: "r"(d), "l"(s));
}
__device__ __forceinline__ void cp_commit() {
    asm volatile("cp.async.commit_group;" ::: "memory");
}
template <int N> __device__ __forceinline__ void cp_wait() {
    asm volatile("cp.async.wait_group %0;" :: "n"(N) : "memory");
}

// ---------------------------------------------------------------------------
// Kernel 0: convert Wg / enc / Wc to fp16 scratch (Wg rows >= Vn zeroed).
// ---------------------------------------------------------------------------
__global__ __launch_bounds__(256) void convert_kernel(
    const float* __restrict__ Wg, const float* __restrict__ enc,
    const float* __restrict__ Wc)
{
    const size_t nWg  = (size_t)VPAD * Hn / 4;
    const size_t nEnc = (size_t)Bn * Tn * H2 / 4;
    const size_t nWc  = (size_t)Hn * H2 / 4;
    const size_t tot  = nWg + nEnc + nWc;
    for (size_t i = (size_t)blockIdx.x * 256 + threadIdx.x; i < tot;
         i += (size_t)gridDim.x * 256) {
        float4 v = make_float4(0.f, 0.f, 0.f, 0.f);
        __half* dst;
        if (i < nWg) {
            size_t e = i * 4;
            if ((e >> 8) < Vn) v = *(const float4*)(Wg + e);
            dst = g_WgH + e;
        } else if (i < nWg + nEnc) {
            size_t e = (i - nWg) * 4;
            v = *(const float4*)(enc + e);
            dst = g_encH + e;
        } else {
            size_t e = (i - nWg - nEnc) * 4;
            v = *(const float4*)(Wc + e);
            dst = g_WcH + e;
        }
        __half2 h0 = __floats2half2_rn(v.x, v.y);
        __half2 h1 = __floats2half2_rn(v.z, v.w);
        uint2 u;
        u.x = *(uint32_t*)&h0;
        u.y = *(uint32_t*)&h1;
        *(uint2*)dst = u;
    }
}

// ---------------------------------------------------------------------------
// Kernel A: GRU cell. 4 batches per block (grid 32), 256 threads.
// ---------------------------------------------------------------------------
__global__ __launch_bounds__(256) void gru_kernel(
    const int* __restrict__ dec_in, const float* __restrict__ enc,
    const int* __restrict__ step,
    const float* __restrict__ prev_state, const float* __restrict__ sel,
    const float* __restrict__ emb,
    const float* __restrict__ W_ih, const float* __restrict__ W_hh,
    const float* __restrict__ b_ih, const float* __restrict__ b_hh,
    const float* __restrict__ Wi_w, const float* __restrict__ Wi_b,
    float* __restrict__ dh_out)
{
    __shared__ __align__(16) float xs[4][XD];
    __shared__ __align__(16) float hs[4][Hn];
    __shared__ __align__(16) float es[4][H2];

    const int b0  = blockIdx.x * 4;
    const int tid = threadIdx.x;
    const int stepv = step ? step[0] : 1;

    for (int i = tid; i < 4 * H2; i += 256) {
        int bb = i >> 9, v = i & 511;
        xs[bb][v] = stepv ? sel[(b0 + bb) * H2 + v] : 0.f;
    }
    for (int i = tid; i < 4 * En; i += 256) {
        int bb = i >> 7, v = i & 127;
        xs[bb][H2 + v] = emb[(size_t)dec_in[b0 + bb] * En + v];
    }
    if (stepv) {
        for (int i = tid; i < 4 * Hn; i += 256) {
            int bb = i >> 8, v = i & 255;
            hs[bb][v] = prev_state[(b0 + bb) * Hn + v];
        }
        __syncthreads();
    } else {
        for (int i = tid; i < 4 * H2; i += 256) {
            int bb = i >> 9, v = i & 511;
            es[bb][v] = enc[((size_t)(b0 + bb) * Tn + (Tn - 1)) * H2 + v];
        }
        __syncthreads();
        const int j = tid;
        const float4* wr = (const float4*)(Wi_w + (size_t)j * H2);
        float bj = Wi_b[j];
        float acc[4] = {bj, bj, bj, bj};
        for (int k = 0; k < H2 / 4; k++) {
            float4 w = wr[k];
            #pragma unroll
            for (int bb = 0; bb < 4; bb++) {
                float4 e = ((const float4*)es[bb])[k];
                acc[bb] += w.x * e.x + w.y * e.y + w.z * e.z + w.w * e.w;
            }
        }
        #pragma unroll
        for (int bb = 0; bb < 4; bb++) hs[bb][j] = acc[bb];
        __syncthreads();
    }

    const int j = tid;
    float gir[4], giz[4], gin[4], ghr[4], ghz[4], ghn[4];
    {
        float v0 = b_ih[j], v1 = b_ih[Hn + j], v2 = b_ih[2 * Hn + j];
        #pragma unroll
        for (int bb = 0; bb < 4; bb++) { gir[bb] = v0; giz[bb] = v1; gin[bb] = v2; }
        const float4* r0 = (const float4*)(W_ih + (size_t)j * XD);
        const float4* r1 = (const float4*)(W_ih + (size_t)(Hn + j) * XD);
        const float4* r2 = (const float4*)(W_ih + (size_t)(2 * Hn + j) * XD);
        for (int k = 0; k < XD / 4; k++) {
            float4 w0 = r0[k], w1 = r1[k], w2 = r2[k];
            #pragma unroll
            for (int bb = 0; bb < 4; bb++) {
                float4 x = ((const float4*)xs[bb])[k];
                gir[bb] += w0.x * x.x + w0.y * x.y + w0.z * x.z + w0.w * x.w;
                giz[bb] += w1.x * x.x + w1.y * x.y + w1.z * x.z + w1.w * x.w;
                gin[bb] += w2.x * x.x + w2.y * x.y + w2.z * x.z + w2.w * x.w;
            }
        }
    }
    {
        float v0 = b_hh[j], v1 = b_hh[Hn + j], v2 = b_hh[2 * Hn + j];
        #pragma unroll
        for (int bb = 0; bb < 4; bb++) { ghr[bb] = v0; ghz[bb] = v1; ghn[bb] = v2; }
        const float4* r0 = (const float4*)(W_hh + (size_t)j * Hn);
        const float4* r1 = (const float4*)(W_hh + (size_t)(Hn + j) * Hn);
        const float4* r2 = (const float4*)(W_hh + (size_t)(2 * Hn + j) * Hn);
        for (int k = 0; k < Hn / 4; k++) {
            float4 w0 = r0[k], w1 = r1[k], w2 = r2[k];
            #pragma unroll
            for (int bb = 0; bb < 4; bb++) {
                float4 x = ((const float4*)hs[bb])[k];
                ghr[bb] += w0.x * x.x + w0.y * x.y + w0.z * x.z + w0.w * x.w;
                ghz[bb] += w1.x * x.x + w1.y * x.y + w1.z * x.z + w1.w * x.w;
                ghn[bb] += w2.x * x.x + w2.y * x.y + w2.z * x.z + w2.w * x.w;
            }
        }
    }
    #pragma unroll
    for (int bb = 0; bb < 4; bb++) {
        float r = 1.f / (1.f + fexp(-(gir[bb] + ghr[bb])));
        float z = 1.f / (1.f + fexp(-(giz[bb] + ghz[bb])));
        float n = ftanh(gin[bb] + r * ghn[bb]);
        dh_out[(b0 + bb) * Hn + j] = (1.f - z) * n + z * hs[bb][j];
    }
}

// ---------------------------------------------------------------------------
// Kernel B: score_g via fp16 mma.sync m16n8k16, cp.async double-buffered.
// Block 128x128xK256, BK=64 (4 chunks), warp 64x32.
// ---------------------------------------------------------------------------
#define GS_AST 264   // As stride (halfs)
#define GS_BST 72    // Bs stride (halfs)
#define GS_ABYTES 67584            // 128*264*2
#define GS_BBYTES 18432            // 128*72*2
__global__ __launch_bounds__(256) void scoreg_mma(
    const float* __restrict__ dh, const float* __restrict__ Wgb)
{
    extern __shared__ __align__(16) char smem_raw[];
    __half* As = (__half*)smem_raw;
    __shared__ float biasS[128];
    const uint32_t sbase = smem_u32(smem_raw);

    const int tid = threadIdx.x;
    const int wid = tid >> 5, lane = tid & 31;
    const int warpM = wid >> 2, warpN = wid & 3;
    const int lr = lane >> 2, lc = lane & 3;
    const int v0 = blockIdx.x * 128;
    const int nvalid = (Vn - v0 < 128) ? (Vn - v0) : 128;

    const __half* gB = g_WgH + (size_t)v0 * Hn;

    // prologue: prefetch B chunks 0 and 1
    #pragma unroll
    for (int p = 0; p < 4; p++) {
        int idx = tid + p * 256;
        int n = idx >> 3, ku = (idx & 7) * 8;
        cpa16(sbase + GS_ABYTES + (uint32_t)(n * GS_BST + ku) * 2,
              gB + (size_t)n * Hn + ku);
    }
    cp_commit();
    #pragma unroll
    for (int p = 0; p < 4; p++) {
        int idx = tid + p * 256;
        int n = idx >> 3, ku = (idx & 7) * 8;
        cpa16(sbase + GS_ABYTES + GS_BBYTES + (uint32_t)(n * GS_BST + ku) * 2,
              gB + (size_t)n * Hn + 64 + ku);
    }
    cp_commit();

    if (tid < 128) {
        int vg = v0 + tid;
        biasS[tid] = (vg < Vn) ? Wgb[vg] : 0.f;
    }
    // A = dh -> fp16 smem (full K=256)
    #pragma unroll
    for (int p = 0; p < 32; p++) {
        int idx = tid + p * 256;
        int m = idx >> 6, c4 = (idx & 63) * 4;
        float4 v = *(const float4*)(dh + m * 256 + c4);
        __half2 h0 = __floats2half2_rn(v.x, v.y);
        __half2 h1 = __floats2half2_rn(v.z, v.w);
        uint32_t* d = (uint32_t*)(As + m * GS_AST + c4);
        d[0] = *(uint32_t*)&h0;
        d[1] = *(uint32_t*)&h1;
    }

    float acc[4][4][4];
    #pragma unroll
    for (int mi = 0; mi < 4; mi++)
        #pragma unroll
        for (int ni = 0; ni < 4; ni++)
            #pragma unroll
            for (int q = 0; q < 4; q++) acc[mi][ni][q] = 0.f;

    for (int kc = 0; kc < 4; kc++) {
        cp_wait<1>();
        __syncthreads();
        const __half* Bc = (__half*)(smem_raw + GS_ABYTES + (kc & 1) * GS_BBYTES);
        const int kb0 = kc * 64;
        #pragma unroll
        for (int ks = 0; ks < 4; ks++) {
            const int kb = kb0 + ks * 16;
            uint32_t af[4][4], bf[4][2];
            #pragma unroll
            for (int mi = 0; mi < 4; mi++) {
                const __half* ap = As + (warpM * 64 + mi * 16 + lr) * GS_AST + kb + 2 * lc;
                af[mi][0] = *(const uint32_t*)(ap);
                af[mi][1] = *(const uint32_t*)(ap + 8 * GS_AST);
                af[mi][2] = *(const uint32_t*)(ap + 8);
                af[mi][3] = *(const uint32_t*)(ap + 8 * GS_AST + 8);
            }
            #pragma unroll
            for (int ni = 0; ni < 4; ni++) {
                const __half* bp = Bc + (warpN * 32 + ni * 8 + lr) * GS_BST + ks * 16 + 2 * lc;
                bf[ni][0] = *(const uint32_t*)(bp);
                bf[ni][1] = *(const uint32_t*)(bp + 8);
            }
            #pragma unroll
            for (int mi = 0; mi < 4; mi++)
                #pragma unroll
                for (int ni = 0; ni < 4; ni++)
                    mma_f16(acc[mi][ni], af[mi], bf[ni]);
        }
        __syncthreads();
        if (kc + 2 < 4) {
            uint32_t ba = sbase + GS_ABYTES + (uint32_t)(kc & 1) * GS_BBYTES;
            const __half* gc = gB + (kc + 2) * 64;
            #pragma unroll
            for (int p = 0; p < 4; p++) {
                int idx = tid + p * 256;
                int n = idx >> 3, ku = (idx & 7) * 8;
                cpa16(ba + (uint32_t)(n * GS_BST + ku) * 2, gc + (size_t)n * Hn + ku);
            }
        }
        cp_commit();
    }

    // stage val+bias into smem [128][132] f32 (reuses As region)
    float* stg = (float*)smem_raw;
    #pragma unroll
    for (int mi = 0; mi < 4; mi++) {
        int row = warpM * 64 + mi * 16 + lr;
        #pragma unroll
        for (int ni = 0; ni < 4; ni++) {
            int col = warpN * 32 + ni * 8 + 2 * lc;
            stg[row * 132 + col]           = acc[mi][ni][0] + biasS[col];
            stg[row * 132 + col + 1]       = acc[mi][ni][1] + biasS[col + 1];
            stg[(row + 8) * 132 + col]     = acc[mi][ni][2] + biasS[col];
            stg[(row + 8) * 132 + col + 1] = acc[mi][ni][3] + biasS[col + 1];
        }
    }
    __syncthreads();

    // warp-per-row: row max, e=exp(v-max), sum, store e
    for (int rb = 0; rb < 16; rb++) {
        int r = wid * 16 + rb;
        float v[4];
        #pragma unroll
        for (int q = 0; q < 4; q++) {
            int c = lane * 4 + q;
            v[q] = (c < nvalid) ? stg[r * 132 + c] : -INFINITY;
        }
        float m = fmaxf(fmaxf(v[0], v[1]), fmaxf(v[2], v[3]));
        #pragma unroll
        for (int off = 16; off > 0; off >>= 1)
            m = fmaxf(m, __shfl_xor_sync(0xffffffffu, m, off));
        float e[4], s = 0.f;
        #pragma unroll
        for (int q = 0; q < 4; q++) { e[q] = fexp(v[q] - m); s += e[q]; }
        #pragma unroll
        for (int off = 16; off > 0; off >>= 1)
            s += __shfl_xor_sync(0xffffffffu, s, off);
        #pragma unroll
        for (int q = 0; q < 4; q++) {
            int c = lane * 4 + q;
            if (c < nvalid) g_score[(size_t)r * Vn + v0 + c] = e[q];
        }
        if (lane == 0) {
            g_pm[r * NTILES + blockIdx.x] = m;
            g_ps[r * NTILES + blockIdx.x] = s;
        }
    }
}

// ---------------------------------------------------------------------------
// Kernel C: score_c via fp16 mma, cp.async pipeline over flattened enc.
// Block 64x256xK512, BK=64 (8 chunks), warp 32x64.
// ---------------------------------------------------------------------------
#define SC_ST 72
#define SC_ABYTES 9216             // 64*72*2
#define SC_BBYTES 36864            // 256*72*2
__global__ __launch_bounds__(256) void scorec_mma(
    const int* __restrict__ encIdx, const float* __restrict__ Wcb,
    const float* __restrict__ dh)
{
    extern __shared__ __align__(16) char smem_raw[];
    __shared__ float biasS[256];
    __shared__ float dh2[2][256];
    __shared__ float red[64][4];
    const uint32_t sbase = smem_u32(smem_raw);

    const int tid = threadIdx.x;
    const int wid = tid >> 5, lane = tid & 31;
    const int warpM = wid >> 2, warpN = wid & 3;
    const int lr = lane >> 2, lc = lane & 3;
    const int r0 = blockIdx.x * 64;
    const int b0 = r0 / Tn;
    const int b1 = (b0 + 1 < Bn) ? b0 + 1 : Bn - 1;

    const __half* gA = g_encH + (size_t)r0 * H2;

    // prologue: chunks 0, 1
    #pragma unroll
    for (int c = 0; c < 2; c++) {
        uint32_t aa = sbase + c * SC_ABYTES;
        uint32_t ba = sbase + 2 * SC_ABYTES + c * SC_BBYTES;
        #pragma unroll
        for (int p = 0; p < 2; p++) {
            int idx = tid + p * 256;
            int m = idx >> 3, ku = (idx & 7) * 8;
            cpa16(aa + (uint32_t)(m * SC_ST + ku) * 2, gA + (size_t)m * H2 + c * 64 + ku);
        }
        #pragma unroll
        for (int p = 0; p < 8; p++) {
            int idx = tid + p * 256;
            int n = idx >> 3, ku = (idx & 7) * 8;
            cpa16(ba + (uint32_t)(n * SC_ST + ku) * 2, g_WcH + (size_t)n * H2 + c * 64 + ku);
        }
        cp_commit();
    }

    biasS[tid] = Wcb[tid];
    for (int i = tid; i < 512; i += 256) {
        int w = i >> 8;
        dh2[w][i & 255] = dh[(w ? b1 : b0) * 256 + (i & 255)];
    }

    float acc[2][8][4];
    #pragma unroll
    for (int mi = 0; mi < 2; mi++)
        #pragma unroll
        for (int ni = 0; ni < 8; ni++)
            #pragma unroll
            for (int q = 0; q < 4; q++) acc[mi][ni][q] = 0.f;

    for (int kc = 0; kc < 8; kc++) {
        cp_wait<1>();
        __syncthreads();
        const int buf = kc & 1;
        const __half* Ac = (__half*)(smem_raw + buf * SC_ABYTES);
        const __half* Bc = (__half*)(smem_raw + 2 * SC_ABYTES + buf * SC_BBYTES);
        #pragma unroll
        for (int ks = 0; ks < 4; ks++) {
            const int kb = ks * 16;
            uint32_t af[2][4], bf[8][2];
            #pragma unroll
            for (int mi = 0; mi < 2; mi++) {
                const __half* ap = Ac + (warpM * 32 + mi * 16 + lr) * SC_ST + kb + 2 * lc;
                af[mi][0] = *(const uint32_t*)(ap);
                af[mi][1] = *(const uint32_t*)(ap + 8 * SC_ST);
                af[mi][2] = *(const uint32_t*)(ap + 8);
                af[mi][3] = *(const uint32_t*)(ap + 8 * SC_ST + 8);
            }
            #pragma unroll
            for (int ni = 0; ni < 8; ni++) {
                const __half* bp = Bc + (warpN * 64 + ni * 8 + lr) * SC_ST + kb + 2 * lc;
                bf[ni][0] = *(const uint32_t*)(bp);
                bf[ni][1] = *(const uint32_t*)(bp + 8);
            }
            #pragma unroll
            for (int mi = 0; mi < 2; mi++)
                #pragma unroll
                for (int ni = 0; ni < 8; ni++)
                    mma_f16(acc[mi][ni], af[mi], bf[ni]);
        }
        __syncthreads();
        if (kc + 2 < 8) {
            uint32_t aa = sbase + buf * SC_ABYTES;
            uint32_t ba = sbase + 2 * SC_ABYTES + buf * SC_BBYTES;
            #pragma unroll
            for (int p = 0; p < 2; p++) {
                int idx = tid + p * 256;
                int m = idx >> 3, ku = (idx & 7) * 8;
                cpa16(aa + (uint32_t)(m * SC_ST + ku) * 2,
                      gA + (size_t)m * H2 + (kc + 2) * 64 + ku);
            }
            #pragma unroll
            for (int p = 0; p < 8; p++) {
                int idx = tid + p * 256;
                int n = idx >> 3, ku = (idx & 7) * 8;
                cpa16(ba + (uint32_t)(n * SC_ST + ku) * 2,
                      g_WcH + (size_t)n * H2 + (kc + 2) * 64 + ku);
            }
        }
        cp_commit();
    }

    // epilogue: per-row sum over this warp's 64 h-columns of tanh(v+b)*dh
    #pragma unroll
    for (int mi = 0; mi < 2; mi++) {
        int rowa = warpM * 32 + mi * 16 + lr;
        int rowb = rowa + 8;
        int ba = (r0 + rowa) / Tn - b0;
        int bb = (r0 + rowb) / Tn - b0;
        float pa = 0.f, pb = 0.f;
        #pragma unroll
        for (int ni = 0; ni < 8; ni++) {
            int col = warpN * 64 + ni * 8 + 2 * lc;
            float t0 = ftanh(acc[mi][ni][0] + biasS[col]);
            float t1 = ftanh(acc[mi][ni][1] + biasS[col + 1]);
            float t2 = ftanh(acc[mi][ni][2] + biasS[col]);
            float t3 = ftanh(acc[mi][ni][3] + biasS[col + 1]);
            pa += t0 * dh2[ba][col] + t1 * dh2[ba][col + 1];
            pb += t2 * dh2[bb][col] + t3 * dh2[bb][col + 1];
        }
        pa += __shfl_xor_sync(0xffffffffu, pa, 1);
        pa += __shfl_xor_sync(0xffffffffu, pa, 2);
        pb += __shfl_xor_sync(0xffffffffu, pb, 1);
        pb += __shfl_xor_sync(0xffffffffu, pb, 2);
        if (lc == 0) {
            red[rowa][warpN] = pa;
            red[rowb][warpN] = pb;
        }
    }
    __syncthreads();
    if (tid < 64) {
        float s = red[tid][0] + red[tid][1] + red[tid][2] + red[tid][3];
        float sc = ftanh(s);
        int gr = r0 + tid;
        if (encIdx[gr] == 0) sc -= 10000.f;
        g_scorec[gr] = sc;
    }
}

// ---------------------------------------------------------------------------
// Kernel D: combine partials; rewrite g_ps as per-tile probability scale.
// ---------------------------------------------------------------------------
__global__ __launch_bounds__(256) void combine_kernel()
{
    __shared__ float red[256];
    const int b = blockIdx.x, tid = threadIdx.x;

    float m = -INFINITY;
    for (int i = tid; i < NTILES; i += 256) m = fmaxf(m, g_pm[b * NTILES + i]);
    for (int i = tid; i < Tn; i += 256)     m = fmaxf(m, g_scorec[b * Tn + i]);
    red[tid] = m; __syncthreads();
    for (int s = 128; s > 0; s >>= 1) {
        if (tid < s) red[tid] = fmaxf(red[tid], red[tid + s]);
        __syncthreads();
    }
    float mx = red[0];
    __syncthreads();

    float s = 0.f;
    for (int i = tid; i < NTILES; i += 256)
        s += g_ps[b * NTILES + i] * fexp(g_pm[b * NTILES + i] - mx);
    for (int i = tid; i < Tn; i += 256)
        s += fexp(g_scorec[b * Tn + i] - mx);
    red[tid] = s; __syncthreads();
    for (int k = 128; k > 0; k >>= 1) {
        if (tid < k) red[tid] += red[tid + k];
        __syncthreads();
    }
    float inv = 1.f / red[0];
    if (tid == 0) { g_max[b] = mx; g_invsum[b] = inv; }
    __syncthreads();
    for (int i = tid; i < NTILES; i += 256)
        g_ps[b * NTILES + i] = fexp(g_pm[b * NTILES + i] - mx) * inv;
}

// ---------------------------------------------------------------------------
// Kernel E: prob_out base = [ e * tile_scale (V) | 1e-4 (OOV) ].
// ---------------------------------------------------------------------------
__global__ __launch_bounds__(256) void probg_kernel(float* __restrict__ out)
{
    int idx = blockIdx.x * 256 + threadIdx.x;
    if (idx >= Bn * PV) return;
    int b = idx / PV, v = idx - b * PV;
    out[idx] = (v < Vn)
        ? g_score[(size_t)b * Vn + v] * g_ps[b * NTILES + (v >> 7)]
        : 1e-4f;
}

// ---------------------------------------------------------------------------
// Kernel F: prob_c, scatter-add into prob_out, selective_read_new.
// ---------------------------------------------------------------------------
__global__ __launch_bounds__(256) void final_kernel(
    const int* __restrict__ dec_in, const int* __restrict__ encIdx,
    const float* __restrict__ enc,
    float* __restrict__ prob_out, float* __restrict__ sel_out)
{
    __shared__ float pc[Tn];
    __shared__ float wt[Tn];
    __shared__ float norm;

    const int b = blockIdx.x, tid = threadIdx.x;
    const float mx = g_max[b], inv = g_invsum[b];
    const int dec = dec_in[b];

    if (tid < Tn) {
        float p = fexp(g_scorec[b * Tn + tid] - mx) * inv;
        pc[tid] = p;
        wt[tid] = (encIdx[b * Tn + tid] == dec) ? 1.f : 0.f;
    }
    __syncthreads();
    if (tid == 0) {
        float t = 0.f;
        for (int i = 0; i < Tn; i++) t += wt[i];
        norm = (t > 1.f) ? 1.f / t : 1.f;
    }
    __syncthreads();
    float nf = norm;
    if (tid < Tn) {
        wt[tid] = wt[tid] * pc[tid] * nf;
        atomicAdd(&prob_out[(size_t)b * PV + encIdx[b * Tn + tid]], pc[tid]);
    }
    __syncthreads();

    const float* encb = enc + (size_t)b * Tn * H2;
    for (int e = tid; e < H2; e += 256) {
        float s = 0.f;
        #pragma unroll 4
        for (int t = 0; t < Tn; t++) s += wt[t] * encb[(size_t)t * H2 + e];
        sel_out[b * H2 + e] = s;
    }
}

// ---------------------------------------------------------------------------
extern "C" void kernel_launch(void* const* d_in, const int* in_sizes, int n_in,
                              void* d_out, int out_size)
{
    const int*   dec  = (const int*)d_in[0];
    const float* enc  = (const float*)d_in[1];
    const int*   eidx = (const int*)d_in[2];
    const float* prev = (const float*)d_in[3];
    const float* sel  = (const float*)d_in[4];
    const int si = (n_in >= 17) ? 1 : 0;
    const int* step = si ? (const int*)d_in[5] : nullptr;
    const float* emb = (const float*)d_in[5 + si];
    const float* Wih = (const float*)d_in[6 + si];
    const float* Whh = (const float*)d_in[7 + si];
    const float* bih = (const float*)d_in[8 + si];
    const float* bhh = (const float*)d_in[9 + si];
    const float* Wiw = (const float*)d_in[10 + si];
    const float* Wib = (const float*)d_in[11 + si];
    const float* Wgw = (const float*)d_in[12 + si];
    const float* Wgb = (const float*)d_in[13 + si];
    const float* Wcw = (const float*)d_in[14 + si];
    const float* Wcb = (const float*)d_in[15 + si];

    float* out    = (float*)d_out;
    float* prob   = out;                       // (B, 1, V+OOV)
    float* dh     = out + (size_t)Bn * PV;     // (B, H)
    float* selnew = dh + Bn * Hn;              // (B, 1, 2H)

    const int SMEM_G = GS_ABYTES + 2 * GS_BBYTES;        // 104448
    const int SMEM_C = 2 * SC_ABYTES + 2 * SC_BBYTES;    // 92160
    cudaFuncSetAttribute(scoreg_mma, cudaFuncAttributeMaxDynamicSharedMemorySize, SMEM_G);
    cudaFuncSetAttribute(scorec_mma, cudaFuncAttributeMaxDynamicSharedMemorySize, SMEM_C);

    convert_kernel<<<8192, 256>>>(Wgw, enc, Wcw);
    gru_kernel<<<Bn / 4, 256>>>(dec, enc, step, prev, sel, emb, Wih, Whh,
                                bih, bhh, Wiw, Wib, dh);
    scoreg_mma<<<NTILES, 256, SMEM_G>>>(dh, Wgb);
    scorec_mma<<<CTILES, 256, SMEM_C>>>(eidx, Wcb, dh);
    combine_kernel<<<Bn, 256>>>();
    probg_kernel<<<(Bn * PV + 255) / 256, 256>>>(prob);
    final_kernel<<<Bn, 256>>>(dec, eidx, enc, prob, selnew);
}

// round 11
// speedup vs baseline: 1.3990x; 1.2577x over previous
#include <cuda_runtime.h>
#include <cuda_fp16.h>
#include <math.h>
#include <stdint.h>

#define Bn   128
#define Tn   200
#define Vn   50257
#define Hn   256
#define En   128
#define OOV  50
#define H2   512
#define XD   640
#define PV   (Vn + OOV)
#define NTILES 393          // ceil(Vn/128)
#define CTILES 400          // 25600/64

__device__ __half g_scoreH[(size_t)Bn * Vn];  // exp(score - tile_max), fp16
__device__ float g_scorec[Bn * Tn];
__device__ float g_pm[Bn * NTILES];
__device__ float g_ps[Bn * NTILES];
__device__ float g_max[Bn];
__device__ float g_invsum[Bn];
__device__ __half g_WcH[Hn * H2];             // fp16 Wc only (0.26 MB)

// ============================ helpers =======================================
__device__ __forceinline__ uint32_t smem_u32(const void* p) {
    uint32_t a;
    asm("{ .reg .u64 t; cvta.to.shared.u64 t, %1; cvt.u32.u64 %0, t; }"
        : "=r"(a) : "l"(p));
    return a;
}
__device__ __forceinline__ float fexp(float x) {
    x = fminf(fmaxf(x, -87.0f), 87.0f);
    float y = x * 1.4426950408889634f;
    float z = y + 12582912.f;
    int   i = __float_as_int(z) - 0x4B400000;
    float f = y - (z - 12582912.f);
    float p = 1.3386276e-3f;
    p = fmaf(p, f, 9.6183633e-3f);
    p = fmaf(p, f, 5.5502813e-2f);
    p = fmaf(p, f, 2.4022652e-1f);
    p = fmaf(p, f, 6.9314720e-1f);
    p = fmaf(p, f, 1.0f);
    return __int_as_float(__float_as_int(p) + (i << 23));
}
__device__ __forceinline__ float ftanh(float x) {
    float ax = fminf(fabsf(x), 15.f);
    float t  = fexp(2.f * ax);
    float d  = t + 1.f;
    float r  = __int_as_float(0x7EF311C3u - __float_as_int(d));
    r = r * fmaf(-d, r, 2.f);
    r = r * fmaf(-d, r, 2.f);
    r = r * fmaf(-d, r, 2.f);
    return copysignf((t - 1.f) * r, x);
}
__device__ __forceinline__ void mma_f16(float c[4], const uint32_t a[4],
                                        const uint32_t b[2]) {
    asm volatile(
        "mma.sync.aligned.m16n8k16.row.col.f32.f16.f16.f32 "
        "{%0,%1,%2,%3}, {%4,%5,%6,%7}, {%8,%9}, {%0,%1,%2,%3};"
        : "+f"(c[0]), "+f"(c[1]), "+f"(c[2]), "+f"(c[3])
        : "r"(a[0]), "r"(a[1]), "r"(a[2]), "r"(a[3]), "r"(b[0]), "r"(b[1]));
}
// pack 2 f32 -> f16x2 (lo = first arg)
__device__ __forceinline__ uint32_t pk16(float lo, float hi) {
    uint32_t r;
    asm("cvt.rn.f16x2.f32 %0, %1, %2;" : "=r"(r) : "f"(hi), "f"(lo));
    return r;
}
__device__ __forceinline__ void cpa16(uint32_t d, const void* s) {
    asm volatile("cp.async.cg.shared.global [%0], [%1], 16;" :: "r"(d), "l"(s));
}
__device__ __forceinline__ void cpa16z(uint32_t d, const void* s, int sz) {
    asm volatile("cp.async.cg.shared.global [%0], [%1], 16, %2;"
                 :: "r"(d), "l"(s), "r"(sz));
}
__device__ __forceinline__ void cp_commit() {
    asm volatile("cp.async.commit_group;" ::: "memory");
}
template <int N> __device__ __forceinline__ void cp_wait() {
    asm volatile("cp.async.wait_group %0;" :: "n"(N) : "memory");
}

// ---------------------------------------------------------------------------
// Kernel 0: convert Wc (256x512 f32 -> fp16). 128 blocks x 256 thr, 1 f4 each.
// ---------------------------------------------------------------------------
__global__ __launch_bounds__(256) void wcconv_kernel(const float* __restrict__ Wc)
{
    int i = blockIdx.x * 256 + threadIdx.x;        // 32768 float4 groups
    float4 v = *(const float4*)(Wc + (size_t)i * 4);
    __half2 h0 = __floats2half2_rn(v.x, v.y);
    __half2 h1 = __floats2half2_rn(v.z, v.w);
    uint2 u;
    u.x = *(uint32_t*)&h0;
    u.y = *(uint32_t*)&h1;
    *(uint2*)(g_WcH + (size_t)i * 4) = u;
}

// ---------------------------------------------------------------------------
// Kernel A: GRU cell. 4 batches per block (grid 32), 256 threads.
// ---------------------------------------------------------------------------
__global__ __launch_bounds__(256) void gru_kernel(
    const int* __restrict__ dec_in, const float* __restrict__ enc,
    const int* __restrict__ step,
    const float* __restrict__ prev_state, const float* __restrict__ sel,
    const float* __restrict__ emb,
    const float* __restrict__ W_ih, const float* __restrict__ W_hh,
    const float* __restrict__ b_ih, const float* __restrict__ b_hh,
    const float* __restrict__ Wi_w, const float* __restrict__ Wi_b,
    float* __restrict__ dh_out)
{
    __shared__ __align__(16) float xs[4][XD];
    __shared__ __align__(16) float hs[4][Hn];
    __shared__ __align__(16) float es[4][H2];

    const int b0  = blockIdx.x * 4;
    const int tid = threadIdx.x;
    const int stepv = step ? step[0] : 1;

    for (int i = tid; i < 4 * H2; i += 256) {
        int bb = i >> 9, v = i & 511;
        xs[bb][v] = stepv ? sel[(b0 + bb) * H2 + v] : 0.f;
    }
    for (int i = tid; i < 4 * En; i += 256) {
        int bb = i >> 7, v = i & 127;
        xs[bb][H2 + v] = emb[(size_t)dec_in[b0 + bb] * En + v];
    }
    if (stepv) {
        for (int i = tid; i < 4 * Hn; i += 256) {
            int bb = i >> 8, v = i & 255;
            hs[bb][v] = prev_state[(b0 + bb) * Hn + v];
        }
        __syncthreads();
    } else {
        for (int i = tid; i < 4 * H2; i += 256) {
            int bb = i >> 9, v = i & 511;
            es[bb][v] = enc[((size_t)(b0 + bb) * Tn + (Tn - 1)) * H2 + v];
        }
        __syncthreads();
        const int j = tid;
        const float4* wr = (const float4*)(Wi_w + (size_t)j * H2);
        float bj = Wi_b[j];
        float acc[4] = {bj, bj, bj, bj};
        for (int k = 0; k < H2 / 4; k++) {
            float4 w = wr[k];
            #pragma unroll
            for (int bb = 0; bb < 4; bb++) {
                float4 e = ((const float4*)es[bb])[k];
                acc[bb] += w.x * e.x + w.y * e.y + w.z * e.z + w.w * e.w;
            }
        }
        #pragma unroll
        for (int bb = 0; bb < 4; bb++) hs[bb][j] = acc[bb];
        __syncthreads();
    }

    const int j = tid;
    float gir[4], giz[4], gin[4], ghr[4], ghz[4], ghn[4];
    {
        float v0 = b_ih[j], v1 = b_ih[Hn + j], v2 = b_ih[2 * Hn + j];
        #pragma unroll
        for (int bb = 0; bb < 4; bb++) { gir[bb] = v0; giz[bb] = v1; gin[bb] = v2; }
        const float4* r0 = (const float4*)(W_ih + (size_t)j * XD);
        const float4* r1 = (const float4*)(W_ih + (size_t)(Hn + j) * XD);
        const float4* r2 = (const float4*)(W_ih + (size_t)(2 * Hn + j) * XD);
        for (int k = 0; k < XD / 4; k++) {
            float4 w0 = r0[k], w1 = r1[k], w2 = r2[k];
            #pragma unroll
            for (int bb = 0; bb < 4; bb++) {
                float4 x = ((const float4*)xs[bb])[k];
                gir[bb] += w0.x * x.x + w0.y * x.y + w0.z * x.z + w0.w * x.w;
                giz[bb] += w1.x * x.x + w1.y * x.y + w1.z * x.z + w1.w * x.w;
                gin[bb] += w2.x * x.x + w2.y * x.y + w2.z * x.z + w2.w * x.w;
            }
        }
    }
    {
        float v0 = b_hh[j], v1 = b_hh[Hn + j], v2 = b_hh[2 * Hn + j];
        #pragma unroll
        for (int bb = 0; bb < 4; bb++) { ghr[bb] = v0; ghz[bb] = v1; ghn[bb] = v2; }
        const float4* r0 = (const float4*)(W_hh + (size_t)j * Hn);
        const float4* r1 = (const float4*)(W_hh + (size_t)(Hn + j) * Hn);
        const float4* r2 = (const float4*)(W_hh + (size_t)(2 * Hn + j) * Hn);
        for (int k = 0; k < Hn / 4; k++) {
            float4 w0 = r0[k], w1 = r1[k], w2 = r2[k];
            #pragma unroll
            for (int bb = 0; bb < 4; bb++) {
                float4 x = ((const float4*)hs[bb])[k];
                ghr[bb] += w0.x * x.x + w0.y * x.y + w0.z * x.z + w0.w * x.w;
                ghz[bb] += w1.x * x.x + w1.y * x.y + w1.z * x.z + w1.w * x.w;
                ghn[bb] += w2.x * x.x + w2.y * x.y + w2.z * x.z + w2.w * x.w;
            }
        }
    }
    #pragma unroll
    for (int bb = 0; bb < 4; bb++) {
        float r = 1.f / (1.f + fexp(-(gir[bb] + ghr[bb])));
        float z = 1.f / (1.f + fexp(-(giz[bb] + ghz[bb])));
        float n = ftanh(gin[bb] + r * ghn[bb]);
        dh_out[(b0 + bb) * Hn + j] = (1.f - z) * n + z * hs[bb][j];
    }
}

// ---------------------------------------------------------------------------
// Kernel B: score_g. Block 128x128xK256. A = dh fp16 smem; B = Wg f32 via
// cp.async (BK=32, double-buffered), converted to f16 in registers.
// ---------------------------------------------------------------------------
#define GS_AST 264                  // As stride (halfs)
#define GS_ABYTES 67584             // 128*264*2
#define GS_BST 36                   // B stride (floats)
#define GS_BBYTES 18432             // 128*36*4
__global__ __launch_bounds__(256) void scoreg_mma(
    const float* __restrict__ dh, const float* __restrict__ Wg,
    const float* __restrict__ Wgb)
{
    extern __shared__ __align__(16) char smem_raw[];
    __half* As = (__half*)smem_raw;
    __shared__ float biasS[128];
    const uint32_t sbase = smem_u32(smem_raw);

    const int tid = threadIdx.x;
    const int wid = tid >> 5, lane = tid & 31;
    const int warpM = wid >> 2, warpN = wid & 3;
    const int lr = lane >> 2, lc = lane & 3;
    const int v0 = blockIdx.x * 128;
    const int nvalid = (Vn - v0 < 128) ? (Vn - v0) : 128;

    auto loadB = [&](int kc2, uint32_t dstb) {
        #pragma unroll
        for (int p = 0; p < 4; p++) {
            int idx = tid + p * 256;
            int row = idx >> 3, q = idx & 7;
            int vg = v0 + row;
            const float* src = Wg + (size_t)(vg < Vn ? vg : Vn - 1) * 256 + kc2 * 32 + q * 4;
            cpa16z(dstb + (uint32_t)(row * GS_BST + q * 4) * 4, src, vg < Vn ? 16 : 0);
        }
    };
    loadB(0, sbase + GS_ABYTES);               cp_commit();
    loadB(1, sbase + GS_ABYTES + GS_BBYTES);   cp_commit();

    if (tid < 128) {
        int vg = v0 + tid;
        biasS[tid] = (vg < Vn) ? Wgb[vg] : 0.f;
    }
    // A = dh -> fp16 smem (full K=256)
    #pragma unroll
    for (int p = 0; p < 32; p++) {
        int idx = tid + p * 256;
        int m = idx >> 6, c4 = (idx & 63) * 4;
        float4 v = *(const float4*)(dh + m * 256 + c4);
        uint32_t* d = (uint32_t*)(As + m * GS_AST + c4);
        d[0] = pk16(v.x, v.y);
        d[1] = pk16(v.z, v.w);
    }

    float acc[4][4][4];
    #pragma unroll
    for (int mi = 0; mi < 4; mi++)
        #pragma unroll
        for (int ni = 0; ni < 4; ni++)
            #pragma unroll
            for (int q = 0; q < 4; q++) acc[mi][ni][q] = 0.f;

    for (int kc = 0; kc < 8; kc++) {
        cp_wait<1>();
        __syncthreads();
        const float* Bc = (const float*)(smem_raw + GS_ABYTES + (kc & 1) * GS_BBYTES);
        #pragma unroll
        for (int ks = 0; ks < 2; ks++) {
            const int kg = kc * 32 + ks * 16;
            uint32_t af[4][4], bf[4][2];
            #pragma unroll
            for (int mi = 0; mi < 4; mi++) {
                const __half* ap = As + (warpM * 64 + mi * 16 + lr) * GS_AST + kg + 2 * lc;
                af[mi][0] = *(const uint32_t*)(ap);
                af[mi][1] = *(const uint32_t*)(ap + 8 * GS_AST);
                af[mi][2] = *(const uint32_t*)(ap + 8);
                af[mi][3] = *(const uint32_t*)(ap + 8 * GS_AST + 8);
            }
            #pragma unroll
            for (int ni = 0; ni < 4; ni++) {
                const float* bp = Bc + (warpN * 32 + ni * 8 + lr) * GS_BST + ks * 16 + 2 * lc;
                float2 u0 = *(const float2*)(bp);
                float2 u1 = *(const float2*)(bp + 8);
                bf[ni][0] = pk16(u0.x, u0.y);
                bf[ni][1] = pk16(u1.x, u1.y);
            }
            #pragma unroll
            for (int mi = 0; mi < 4; mi++)
                #pragma unroll
                for (int ni = 0; ni < 4; ni++)
                    mma_f16(acc[mi][ni], af[mi], bf[ni]);
        }
        __syncthreads();
        if (kc + 2 < 8)
            loadB(kc + 2, sbase + GS_ABYTES + (uint32_t)(kc & 1) * GS_BBYTES);
        cp_commit();
    }

    // stage val+bias into smem [128][132] f32 (reuses As region)
    float* stg = (float*)smem_raw;
    #pragma unroll
    for (int mi = 0; mi < 4; mi++) {
        int row = warpM * 64 + mi * 16 + lr;
        #pragma unroll
        for (int ni = 0; ni < 4; ni++) {
            int col = warpN * 32 + ni * 8 + 2 * lc;
            stg[row * 132 + col]           = acc[mi][ni][0] + biasS[col];
            stg[row * 132 + col + 1]       = acc[mi][ni][1] + biasS[col + 1];
            stg[(row + 8) * 132 + col]     = acc[mi][ni][2] + biasS[col];
            stg[(row + 8) * 132 + col + 1] = acc[mi][ni][3] + biasS[col + 1];
        }
    }
    __syncthreads();

    // warp-per-row: row max, e=exp(v-max) -> fp16 g_scoreH, sum
    for (int rb = 0; rb < 16; rb++) {
        int r = wid * 16 + rb;
        float v[4];
        #pragma unroll
        for (int q = 0; q < 4; q++) {
            int c = lane * 4 + q;
            v[q] = (c < nvalid) ? stg[r * 132 + c] : -INFINITY;
        }
        float m = fmaxf(fmaxf(v[0], v[1]), fmaxf(v[2], v[3]));
        #pragma unroll
        for (int off = 16; off > 0; off >>= 1)
            m = fmaxf(m, __shfl_xor_sync(0xffffffffu, m, off));
        float e[4], s = 0.f;
        #pragma unroll
        for (int q = 0; q < 4; q++) { e[q] = fexp(v[q] - m); s += e[q]; }
        #pragma unroll
        for (int off = 16; off > 0; off >>= 1)
            s += __shfl_xor_sync(0xffffffffu, s, off);
        #pragma unroll
        for (int q = 0; q < 4; q++) {
            int c = lane * 4 + q;
            if (c < nvalid) g_scoreH[(size_t)r * Vn + v0 + c] = __float2half_rn(e[q]);
        }
        if (lane == 0) {
            g_pm[r * NTILES + blockIdx.x] = m;
            g_ps[r * NTILES + blockIdx.x] = s;
        }
    }
}

// ---------------------------------------------------------------------------
// Kernel C: score_c. Block 64x256xK512. A = enc f32 via cp.async (reg cvt);
// B = Wc fp16 via cp.async. Epilogue: tanh(P+b).dh -> tanh -> mask.
// ---------------------------------------------------------------------------
#define SC_AST 68                   // A stride (floats)
#define SC_ABYTES 17408             // 64*68*4
#define SC_BST 72                   // B stride (halfs)
#define SC_BBYTES 36864             // 256*72*2
__global__ __launch_bounds__(256) void scorec_mma(
    const float* __restrict__ enc, const int* __restrict__ encIdx,
    const float* __restrict__ Wcb, const float* __restrict__ dh)
{
    extern __shared__ __align__(16) char smem_raw[];
    __shared__ float biasS[256];
    __shared__ float dh2[2][256];
    __shared__ float red[64][4];
    const uint32_t sbase = smem_u32(smem_raw);

    const int tid = threadIdx.x;
    const int wid = tid >> 5, lane = tid & 31;
    const int warpM = wid >> 2, warpN = wid & 3;
    const int lr = lane >> 2, lc = lane & 3;
    const int r0 = blockIdx.x * 64;
    const int b0 = r0 / Tn;
    const int b1 = (b0 + 1 < Bn) ? b0 + 1 : Bn - 1;

    const float* gA = enc + (size_t)r0 * H2;

    auto loadA = [&](int kc2, uint32_t dstb) {
        #pragma unroll
        for (int p = 0; p < 4; p++) {
            int idx = tid + p * 256;
            int m = idx >> 4, q = idx & 15;
            cpa16(dstb + (uint32_t)(m * SC_AST + q * 4) * 4,
                  gA + (size_t)m * H2 + kc2 * 64 + q * 4);
        }
    };
    auto loadB = [&](int kc2, uint32_t dstb) {
        #pragma unroll
        for (int p = 0; p < 8; p++) {
            int idx = tid + p * 256;
            int n = idx >> 3, ku = (idx & 7) * 8;
            cpa16(dstb + (uint32_t)(n * SC_BST + ku) * 2,
                  g_WcH + (size_t)n * H2 + kc2 * 64 + ku);
        }
    };
    loadA(0, sbase);  loadB(0, sbase + 2 * SC_ABYTES);                cp_commit();
    loadA(1, sbase + SC_ABYTES);  loadB(1, sbase + 2 * SC_ABYTES + SC_BBYTES);  cp_commit();

    biasS[tid] = Wcb[tid];
    for (int i = tid; i < 512; i += 256) {
        int w = i >> 8;
        dh2[w][i & 255] = dh[(w ? b1 : b0) * 256 + (i & 255)];
    }

    float acc[2][8][4];
    #pragma unroll
    for (int mi = 0; mi < 2; mi++)
        #pragma unroll
        for (int ni = 0; ni < 8; ni++)
            #pragma unroll
            for (int q = 0; q < 4; q++) acc[mi][ni][q] = 0.f;

    for (int kc = 0; kc < 8; kc++) {
        cp_wait<1>();
        __syncthreads();
        const int buf = kc & 1;
        const float* Ac = (const float*)(smem_raw + buf * SC_ABYTES);
        const __half* Bc = (const __half*)(smem_raw + 2 * SC_ABYTES + buf * SC_BBYTES);
        #pragma unroll
        for (int ks = 0; ks < 4; ks++) {
            const int kb = ks * 16;
            uint32_t af[2][4], bf[8][2];
            #pragma unroll
            for (int mi = 0; mi < 2; mi++) {
                const float* ap = Ac + (warpM * 32 + mi * 16 + lr) * SC_AST + kb + 2 * lc;
                float2 u0 = *(const float2*)(ap);
                float2 u1 = *(const float2*)(ap + 8 * SC_AST);
                float2 u2 = *(const float2*)(ap + 8);
                float2 u3 = *(const float2*)(ap + 8 * SC_AST + 8);
                af[mi][0] = pk16(u0.x, u0.y);
                af[mi][1] = pk16(u1.x, u1.y);
                af[mi][2] = pk16(u2.x, u2.y);
                af[mi][3] = pk16(u3.x, u3.y);
            }
            #pragma unroll
            for (int ni = 0; ni < 8; ni++) {
                const __half* bp = Bc + (warpN * 64 + ni * 8 + lr) * SC_BST + kb + 2 * lc;
                bf[ni][0] = *(const uint32_t*)(bp);
                bf[ni][1] = *(const uint32_t*)(bp + 8);
            }
            #pragma unroll
            for (int mi = 0; mi < 2; mi++)
                #pragma unroll
                for (int ni = 0; ni < 8; ni++)
                    mma_f16(acc[mi][ni], af[mi], bf[ni]);
        }
        __syncthreads();
        if (kc + 2 < 8) {
            loadA(kc + 2, sbase + (uint32_t)buf * SC_ABYTES);
            loadB(kc + 2, sbase + 2 * SC_ABYTES + (uint32_t)buf * SC_BBYTES);
        }
        cp_commit();
    }

    #pragma unroll
    for (int mi = 0; mi < 2; mi++) {
        int rowa = warpM * 32 + mi * 16 + lr;
        int rowb = rowa + 8;
        int ba = (r0 + rowa) / Tn - b0;
        int bb = (r0 + rowb) / Tn - b0;
        float pa = 0.f, pb = 0.f;
        #pragma unroll
        for (int ni = 0; ni < 8; ni++) {
            int col = warpN * 64 + ni * 8 + 2 * lc;
            float t0 = ftanh(acc[mi][ni][0] + biasS[col]);
            float t1 = ftanh(acc[mi][ni][1] + biasS[col + 1]);
            float t2 = ftanh(acc[mi][ni][2] + biasS[col]);
            float t3 = ftanh(acc[mi][ni][3] + biasS[col + 1]);
            pa += t0 * dh2[ba][col] + t1 * dh2[ba][col + 1];
            pb += t2 * dh2[bb][col] + t3 * dh2[bb][col + 1];
        }
        pa += __shfl_xor_sync(0xffffffffu, pa, 1);
        pa += __shfl_xor_sync(0xffffffffu, pa, 2);
        pb += __shfl_xor_sync(0xffffffffu, pb, 1);
        pb += __shfl_xor_sync(0xffffffffu, pb, 2);
        if (lc == 0) {
            red[rowa][warpN] = pa;
            red[rowb][warpN] = pb;
        }
    }
    __syncthreads();
    if (tid < 64) {
        float s = red[tid][0] + red[tid][1] + red[tid][2] + red[tid][3];
        float sc = ftanh(s);
        int gr = r0 + tid;
        if (encIdx[gr] == 0) sc -= 10000.f;
        g_scorec[gr] = sc;
    }
}

// ---------------------------------------------------------------------------
// Kernel D: combine partials; rewrite g_ps as per-tile probability scale.
// ---------------------------------------------------------------------------
__global__ __launch_bounds__(256) void combine_kernel()
{
    __shared__ float red[256];
    const int b = blockIdx.x, tid = threadIdx.x;

    float m = -INFINITY;
    for (int i = tid; i < NTILES; i += 256) m = fmaxf(m, g_pm[b * NTILES + i]);
    for (int i = tid; i < Tn; i += 256)     m = fmaxf(m, g_scorec[b * Tn + i]);
    red[tid] = m; __syncthreads();
    for (int s = 128; s > 0; s >>= 1) {
        if (tid < s) red[tid] = fmaxf(red[tid], red[tid + s]);
        __syncthreads();
    }
    float mx = red[0];
    __syncthreads();

    float s = 0.f;
    for (int i = tid; i < NTILES; i += 256)
        s += g_ps[b * NTILES + i] * fexp(g_pm[b * NTILES + i] - mx);
    for (int i = tid; i < Tn; i += 256)
        s += fexp(g_scorec[b * Tn + i] - mx);
    red[tid] = s; __syncthreads();
    for (int k = 128; k > 0; k >>= 1) {
        if (tid < k) red[tid] += red[tid + k];
        __syncthreads();
    }
    float inv = 1.f / red[0];
    if (tid == 0) { g_max[b] = mx; g_invsum[b] = inv; }
    __syncthreads();
    for (int i = tid; i < NTILES; i += 256)
        g_ps[b * NTILES + i] = fexp(g_pm[b * NTILES + i] - mx) * inv;
}

// ---------------------------------------------------------------------------
// Kernel E: prob_out base = [ e(fp16) * tile_scale (V) | 1e-4 (OOV) ].
// ---------------------------------------------------------------------------
__global__ __launch_bounds__(256) void probg_kernel(float* __restrict__ out)
{
    int idx = blockIdx.x * 256 + threadIdx.x;
    if (idx >= Bn * PV) return;
    int b = idx / PV, v = idx - b * PV;
    out[idx] = (v < Vn)
        ? __half2float(g_scoreH[(size_t)b * Vn + v]) * g_ps[b * NTILES + (v >> 7)]
        : 1e-4f;
}

// ---------------------------------------------------------------------------
// Kernel F1: selective_read (independent of prob_out). grid (2, Bn).
// ---------------------------------------------------------------------------
__global__ __launch_bounds__(256) void selread_kernel(
    const int* __restrict__ dec_in, const int* __restrict__ encIdx,
    const float* __restrict__ enc, float* __restrict__ sel_out)
{
    __shared__ float wt[Tn];
    __shared__ float norm;

    const int b = blockIdx.y, tid = threadIdx.x;
    const float mx = g_max[b], inv = g_invsum[b];
    const int dec = dec_in[b];

    if (tid < Tn)
        wt[tid] = (encIdx[b * Tn + tid] == dec) ? 1.f : 0.f;
    __syncthreads();
    if (tid == 0) {
        float t = 0.f;
        for (int i = 0; i < Tn; i++) t += wt[i];
        norm = (t > 1.f) ? 1.f / t : 1.f;
    }
    __syncthreads();
    if (tid < Tn)
        wt[tid] *= fexp(g_scorec[b * Tn + tid] - mx) * inv * norm;
    __syncthreads();

    const int e = blockIdx.x * 256 + tid;
    const float* encb = enc + (size_t)b * Tn * H2;
    float s = 0.f;
    #pragma unroll 4
    for (int t = 0; t < Tn; t++) s += wt[t] * encb[(size_t)t * H2 + e];
    sel_out[b * H2 + e] = s;
}

// ---------------------------------------------------------------------------
// Kernel F2: scatter prob_c into prob_out (after probg base write).
// ---------------------------------------------------------------------------
__global__ __launch_bounds__(256) void scatter_kernel(
    const int* __restrict__ encIdx, float* __restrict__ prob_out)
{
    const int b = blockIdx.x, tid = threadIdx.x;
    if (tid < Tn) {
        float p = fexp(g_scorec[b * Tn + tid] - g_max[b]) * g_invsum[b];
        atomicAdd(&prob_out[(size_t)b * PV + encIdx[b * Tn + tid]], p);
    }
}

// ---------------------------------------------------------------------------
extern "C" void kernel_launch(void* const* d_in, const int* in_sizes, int n_in,
                              void* d_out, int out_size)
{
    const int*   dec  = (const int*)d_in[0];
    const float* enc  = (const float*)d_in[1];
    const int*   eidx = (const int*)d_in[2];
    const float* prev = (const float*)d_in[3];
    const float* sel  = (const float*)d_in[4];
    const int si = (n_in >= 17) ? 1 : 0;
    const int* step = si ? (const int*)d_in[5] : nullptr;
    const float* emb = (const float*)d_in[5 + si];
    const float* Wih = (const float*)d_in[6 + si];
    const float* Whh = (const float*)d_in[7 + si];
    const float* bih = (const float*)d_in[8 + si];
    const float* bhh = (const float*)d_in[9 + si];
    const float* Wiw = (const float*)d_in[10 + si];
    const float* Wib = (const float*)d_in[11 + si];
    const float* Wgw = (const float*)d_in[12 + si];
    const float* Wgb = (const float*)d_in[13 + si];
    const float* Wcw = (const float*)d_in[14 + si];
    const float* Wcb = (const float*)d_in[15 + si];

    float* out    = (float*)d_out;
    float* prob   = out;                       // (B, 1, V+OOV)
    float* dh     = out + (size_t)Bn * PV;     // (B, H)
    float* selnew = dh + Bn * Hn;              // (B, 1, 2H)

    const int SMEM_G = GS_ABYTES + 2 * GS_BBYTES;        // 104448
    const int SMEM_C = 2 * SC_ABYTES + 2 * SC_BBYTES;    // 108544
    cudaFuncSetAttribute(scoreg_mma, cudaFuncAttributeMaxDynamicSharedMemorySize, SMEM_G);
    cudaFuncSetAttribute(scorec_mma, cudaFuncAttributeMaxDynamicSharedMemorySize, SMEM_C);

    // static streams/events: created on the (uncaptured) correctness call
    static cudaStream_t s1 = 0;
    static cudaEvent_t evA = 0, evG = 0, evC = 0, evD = 0, evE = 0;
    static int sinit = 0;
    if (!sinit) {
        sinit = 1;
        if (cudaStreamCreateWithFlags(&s1, cudaStreamNonBlocking) == cudaSuccess) {
            bool ok = true;
            ok &= cudaEventCreateWithFlags(&evA, cudaEventDisableTiming) == cudaSuccess;
            ok &= cudaEventCreateWithFlags(&evG, cudaEventDisableTiming) == cudaSuccess;
            ok &= cudaEventCreateWithFlags(&evC, cudaEventDisableTiming) == cudaSuccess;
            ok &= cudaEventCreateWithFlags(&evD, cudaEventDisableTiming) == cudaSuccess;
            ok &= cudaEventCreateWithFlags(&evE, cudaEventDisableTiming) == cudaSuccess;
            if (!ok) s1 = 0;
        } else {
            s1 = 0;
        }
    }

    if (s1) {
        cudaEventRecord(evA, 0);
        cudaStreamWaitEvent(s1, evA, 0);
        wcconv_kernel<<<128, 256, 0, s1>>>(Wcw);                       // s1
        gru_kernel<<<Bn / 4, 256>>>(dec, enc, step, prev, sel, emb,    // s0
                                    Wih, Whh, bih, bhh, Wiw, Wib, dh);
        cudaEventRecord(evG, 0);
        cudaStreamWaitEvent(s1, evG, 0);
        scoreg_mma<<<NTILES, 256, SMEM_G>>>(dh, Wgw, Wgb);             // s0
        scorec_mma<<<CTILES, 256, SMEM_C, s1>>>(enc, eidx, Wcb, dh);   // s1
        cudaEventRecord(evC, s1);
        cudaStreamWaitEvent(0, evC, 0);
        combine_kernel<<<Bn, 256>>>();                                 // s0
        cudaEventRecord(evD, 0);
        cudaStreamWaitEvent(s1, evD, 0);
        selread_kernel<<<dim3(2, Bn), 256, 0, s1>>>(dec, eidx, enc, selnew); // s1
        cudaEventRecord(evE, s1);
        probg_kernel<<<(Bn * PV + 255) / 256, 256>>>(prob);            // s0
        scatter_kernel<<<Bn, 256>>>(eidx, prob);                       // s0
        cudaStreamWaitEvent(0, evE, 0);                                // join
    } else {
        wcconv_kernel<<<128, 256>>>(Wcw);
        gru_kernel<<<Bn / 4, 256>>>(dec, enc, step, prev, sel, emb,
                                    Wih, Whh, bih, bhh, Wiw, Wib, dh);
        scoreg_mma<<<NTILES, 256, SMEM_G>>>(dh, Wgw, Wgb);
        scorec_mma<<<CTILES, 256, SMEM_C>>>(enc, eidx, Wcb, dh);
        combine_kernel<<<Bn, 256>>>();
        probg_kernel<<<(Bn * PV + 255) / 256, 256>>>(prob);
        selread_kernel<<<dim3(2, Bn), 256>>>(dec, eidx, enc, selnew);
        scatter_kernel<<<Bn, 256>>>(eidx, prob);
    }
}